// round 17
// baseline (speedup 1.0000x reference)
#include <cuda_runtime.h>
#include <cuda_fp16.h>
#include <cstdint>

// B=4, N=2048, F_in=128, F_out=64, H=4
#define Bx 4
#define Nx 2048
#define FIN 128
#define FOUT 64
#define Hx 4
#define ALPHA 0.2f

#define MT 128
#define JT 128
#define NTILES (Nx / JT)
#define TSH 136                 // halves per attn smem B row
#define TSH32 (TSH / 2)
#define HT_TILE_H (64 * 128)    // halves per (b,h,jt) htT tile

// Scratch
__device__ __half g_htT[(size_t)Bx * Hx * NTILES * HT_TILE_H];   // 4 MB
__device__ __half g_Wb16[272 * FIN];                             // 68 KB
__device__ float g_esrcT[Bx * Hx * Nx];
__device__ float2 g_edpm[Bx * Hx * Nx];                          // (exp(ed), exp(.2 ed))
__device__ uint32_t g_adjbits[Nx * (Nx / 32)];                   // 512 KB
__device__ uint32_t g_maxd_u[Bx * Hx];

// attn smem: 3-stage pipeline, 20480 B per stage
#define STAGE_BYTES 20480
#define ST_ED 17408
#define ST_BITS 18432
#define SM_ATTN (3 * STAGE_BYTES)           // 61440

// proj smem (u32 offsets)
#define PA32 0
#define PB32 (64 * 68)
#define SM_PROJ ((64 * 68 + 272 * 68) * 4)
#define TRS 72

__device__ __forceinline__ float ex2f(float x) {
    float r;
    asm("ex2.approx.ftz.f32 %0, %1;" : "=f"(r) : "f"(x));
    return r;
}
__device__ __forceinline__ uint32_t enc_f(float f) {
    uint32_t u = __float_as_uint(f);
    return (u & 0x80000000u) ? ~u : (u | 0x80000000u);
}
__device__ __forceinline__ uint32_t smem_u32(const void* p) {
    uint32_t a;
    asm("{ .reg .u64 t; cvta.to.shared.u64 t, %1; cvt.u32.u64 %0, t; }" : "=r"(a) : "l"(p));
    return a;
}
__device__ __forceinline__ void cpa16(uint32_t dst, const void* src) {
    asm volatile("cp.async.cg.shared.global [%0], [%1], 16;" :: "r"(dst), "l"(src));
}

// ---------------------------------------------------------------------------
// Kernel 0 (prep): blocks 0..511 = adj bitmask with batched loads (MLP=8);
// blocks 512..515 = W transpose-pack + wa columns + pad + maxd init.
// ---------------------------------------------------------------------------
__global__ __launch_bounds__(256) void prep_kernel(
    const float* __restrict__ adj, const float* __restrict__ W,
    const float* __restrict__ a)
{
    __shared__ float W_s[FIN][68];
    __shared__ float a_s[2 * FOUT];

    const int t = threadIdx.x;
    if (blockIdx.x < 512) {
        const int gw = blockIdx.x * 8 + (t >> 5);
        const int lane = t & 31;
        const int g = lane >> 3;
        const int sh = (lane & 7) * 4;
        const uint32_t gmask = 0xFFu << (g * 8);
        const float4* src = (const float4*)(adj + (size_t)gw * 1024) + lane;

        // phase 1: batch all 8 loads (MLP = 8)
        float4 v[8];
#pragma unroll
        for (int it = 0; it < 8; it++) v[it] = src[it * 32];

        // phase 2: pack + reduce + store
#pragma unroll
        for (int it = 0; it < 8; it++) {
            uint32_t nib = (v[it].x > 0.5f ? 1u : 0u) | (v[it].y > 0.5f ? 2u : 0u)
                         | (v[it].z > 0.5f ? 4u : 0u) | (v[it].w > 0.5f ? 8u : 0u);
            uint32_t word = __reduce_or_sync(gmask, nib << sh);
            if ((lane & 7) == 0) g_adjbits[gw * 32 + it * 4 + g] = word;
        }
        return;
    }

    const int hh = blockIdx.x - 512;
    {
        const float4* src = (const float4*)(W + (size_t)hh * FIN * FOUT);
#pragma unroll
        for (int k = 0; k < 8; k++) {
            int idx = t + 256 * k;
            int i = idx >> 4, fq = idx & 15;
            *(float4*)&W_s[i][fq * 4] = src[idx];
        }
    }
    if (t < 2 * FOUT) a_s[t] = a[hh * 2 * FOUT + t];
    __syncthreads();

    {
        const int f = t >> 2, q = t & 3;
        __half* dst = g_Wb16 + (hh * 64 + f) * FIN + q * 32;
#pragma unroll
        for (int w = 0; w < 4; w++) {
            const int i0 = q * 32 + w * 8;
            __half2 p;
            uint4 u;
            p = __floats2half2_rn(W_s[i0 + 0][f], W_s[i0 + 1][f]); u.x = *(uint32_t*)&p;
            p = __floats2half2_rn(W_s[i0 + 2][f], W_s[i0 + 3][f]); u.y = *(uint32_t*)&p;
            p = __floats2half2_rn(W_s[i0 + 4][f], W_s[i0 + 5][f]); u.z = *(uint32_t*)&p;
            p = __floats2half2_rn(W_s[i0 + 6][f], W_s[i0 + 7][f]); u.w = *(uint32_t*)&p;
            *(uint4*)(dst + w * 8) = u;
        }
    }

    if (t < FIN) {
        float ssrc = 0.f, sdst = 0.f;
#pragma unroll 8
        for (int f = 0; f < FOUT; f++) {
            float wv = W_s[t][f];
            ssrc = fmaf(wv, a_s[f], ssrc);
            sdst = fmaf(wv, a_s[FOUT + f], sdst);
        }
        g_Wb16[(256 + 2 * hh) * FIN + t] = __float2half(ssrc);
        g_Wb16[(256 + 2 * hh + 1) * FIN + t] = __float2half(sdst);
    }

    if (hh == 0) {
        ((uint2*)(g_Wb16 + 264 * FIN))[t & 127] = make_uint2(0u, 0u);
        if (t < Bx * Hx) g_maxd_u[t] = 0u;
    }
}

// ---------------------------------------------------------------------------
// Kernel 1: projection GEMM (fp16 mma), e columns fused.
// ---------------------------------------------------------------------------
__global__ __launch_bounds__(256) void gat_proj_mma(const float* __restrict__ h)
{
    extern __shared__ char smraw[];
    uint32_t* smu = (uint32_t*)smraw;
    __half* tr = (__half*)(smraw + PB32 * 4);

    const int t = threadIdx.x, lane = t & 31, wid = t >> 5;
    const int gq = lane >> 2, tq = lane & 3;
    const int rowg = wid & 3, colg = wid >> 2;
    const int rowbase = blockIdx.x * 64;
    const int b = rowbase >> 11;
    const int nbase = rowbase & (Nx - 1);
    const float L2E = 1.4426950408889634f;

    {
        const float4* src = (const float4*)(h + (size_t)rowbase * FIN);
#pragma unroll
        for (int k = 0; k < 8; k++) {
            int idx = t + 256 * k;
            int r = idx >> 5, c4 = idx & 31;
            float4 v = src[idx];
            __half2 p0 = __floats2half2_rn(v.x, v.y);
            __half2 p1 = __floats2half2_rn(v.z, v.w);
            *(uint2*)&smu[PA32 + r * 68 + c4 * 2] =
                make_uint2(*(uint32_t*)&p0, *(uint32_t*)&p1);
        }
    }
    {
        const uint4* src = (const uint4*)g_Wb16;
#pragma unroll
        for (int k = 0; k < 17; k++) {
            int idx = t + 256 * k;
            int r = idx >> 4, c = idx & 15;
            *(uint4*)&smu[PB32 + r * 68 + c * 4] = src[idx];
        }
    }
    __syncthreads();

    float acc[17][4];
#pragma unroll
    for (int nt = 0; nt < 17; nt++)
#pragma unroll
        for (int i = 0; i < 4; i++) acc[nt][i] = 0.f;

    const int ntmax = 17 - colg;
#pragma unroll
    for (int ch = 0; ch < 8; ch++) {
        const uint32_t ab = PA32 + (rowg * 16 + gq) * 68 + ch * 8 + tq;
        uint32_t a0 = smu[ab];
        uint32_t a1 = smu[ab + 8 * 68];
        uint32_t a2 = smu[ab + 4];
        uint32_t a3 = smu[ab + 8 * 68 + 4];
#pragma unroll
        for (int nt = 0; nt < 17; nt++) {
            if (nt < ntmax) {
                const uint32_t bb = PB32 + (colg * 136 + nt * 8 + gq) * 68 + ch * 8 + tq;
                uint32_t b0 = smu[bb];
                uint32_t b1 = smu[bb + 4];
                asm volatile(
                    "mma.sync.aligned.m16n8k16.row.col.f32.f16.f16.f32 "
                    "{%0,%1,%2,%3},{%4,%5,%6,%7},{%8,%9},{%0,%1,%2,%3};"
                    : "+f"(acc[nt][0]), "+f"(acc[nt][1]),
                      "+f"(acc[nt][2]), "+f"(acc[nt][3])
                    : "r"(a0), "r"(a1), "r"(a2), "r"(a3), "r"(b0), "r"(b1));
            }
        }
    }
    __syncthreads();

    if (colg == 1) {
        const int n = nbase + rowg * 16 + gq;
        const int bh = b * Hx + tq;
        const float ed0 = acc[15][1], ed1 = acc[15][3];
        g_esrcT[bh * Nx + n] = acc[15][0];
        g_esrcT[bh * Nx + n + 8] = acc[15][2];
        g_edpm[bh * Nx + n] = make_float2(ex2f(ed0 * L2E), ex2f(ed0 * (ALPHA * L2E)));
        g_edpm[bh * Nx + n + 8] = make_float2(ex2f(ed1 * L2E), ex2f(ed1 * (ALPHA * L2E)));
        uint32_t u = enc_f(ed0);
        uint32_t u2 = enc_f(ed1);
        u = u > u2 ? u : u2;
#pragma unroll
        for (int off = 4; off < 32; off <<= 1) {
            uint32_t o = __shfl_xor_sync(0xffffffffu, u, off);
            u = u > o ? u : o;
        }
        if (gq == 0) atomicMax(&g_maxd_u[bh], u);
    }

    {
        const int r = rowg * 16 + gq;
        const int ntht = colg ? 15 : 17;
#pragma unroll
        for (int nt = 0; nt < 17; nt++) {
            if (nt < ntht) {
                const int col = colg * 136 + nt * 8 + 2 * tq;
                tr[col * TRS + r] = __float2half(acc[nt][0]);
                tr[(col + 1) * TRS + r] = __float2half(acc[nt][1]);
                tr[col * TRS + r + 8] = __float2half(acc[nt][2]);
                tr[(col + 1) * TRS + r + 8] = __float2half(acc[nt][3]);
            }
        }
    }
    __syncthreads();

    {
        const int jt = nbase >> 7;
        const int jc0 = nbase & 127;
        const int f = t >> 2, q = t & 3;
#pragma unroll
        for (int hh = 0; hh < Hx; hh++) {
            const int c = hh * 64 + f;
            __half* dst = g_htT + ((size_t)(b * Hx + hh) * NTILES + jt) * HT_TILE_H
                        + f * 128 + jc0;
            ((uint4*)dst)[q] = *(uint4*)&tr[c * TRS + q * 8];
            ((uint4*)dst)[q + 4] = *(uint4*)&tr[c * TRS + (q + 4) * 8];
        }
    }
}

// ---------------------------------------------------------------------------
// attn tile prefetch
// ---------------------------------------------------------------------------
__device__ __forceinline__ void attn_prefetch(
    uint32_t stg, int jt, int t,
    const __half* hsrc0, const float2* edbase, const uint32_t* bitbase)
{
    const char* srcB = (const char*)(hsrc0 + (size_t)jt * HT_TILE_H);
#pragma unroll
    for (int k = 0; k < 4; k++) {
        int idx = t + 256 * k;
        int r = idx >> 4, c = idx & 15;
        cpa16(stg + r * 272 + c * 16, srcB + idx * 16);
    }
    if (t < 64) cpa16(stg + ST_ED + t * 16, (const char*)(edbase + jt * 128) + t * 16);
    if (t < 128) cpa16(stg + ST_BITS + t * 16, (const char*)(bitbase + t * 64 + jt * 4));
    asm volatile("cp.async.commit_group;");
}

// ---------------------------------------------------------------------------
// Kernel 2: flash attention, 3-stage cp.async pipeline.
// ---------------------------------------------------------------------------
__global__ __launch_bounds__(256, 2) void gat_attn_mma(float* __restrict__ out)
{
    extern __shared__ char smraw[];

    const int t = threadIdx.x, lane = t & 31, wid = t >> 5;
    const int gq = lane >> 2, tq = lane & 3;
    const int b = blockIdx.z, hh = blockIdx.y, m0 = blockIdx.x * MT;
    const int bh = b * Hx + hh;
    const int mg = wid & 3, khalf = wid >> 2;
    const float L2E = 1.4426950408889634f;
    const uint32_t sbase = smem_u32(smraw);

    const __half* hsrc0 = g_htT + (size_t)bh * NTILES * HT_TILE_H;
    const uint32_t* bitbase = g_adjbits + (size_t)m0 * (Nx / 32);
    const float2* edbase = g_edpm + (size_t)bh * Nx;

    attn_prefetch(sbase, 0, t, hsrc0, edbase, bitbase);
    attn_prefetch(sbase + STAGE_BYTES, 1, t, hsrc0, edbase, bitbase);

    const uint32_t mu = g_maxd_u[bh];
    const float maxd = (mu >> 31) ? __uint_as_float(mu & 0x7FFFFFFFu)
                                  : __uint_as_float(~mu);
    float Esp[4], Esm[4];
#pragma unroll
    for (int i = 0; i < 4; i++) {
        const float es = g_esrcT[bh * Nx + m0 + mg * 32 + gq + 8 * i];
        const float c = fmaxf(0.f, es + maxd) * L2E;
        Esp[i] = ex2f(es * L2E - c);
        Esm[i] = ex2f(es * (ALPHA * L2E) - c);
    }

    const uint32_t ldmOff =
        2u * ((((lane >> 4) & 1) * 8 + (lane & 7)) * TSH + khalf * 64 + ((lane >> 3) & 1) * 8);

    float acc[2][8][4];
#pragma unroll
    for (int mt = 0; mt < 2; mt++)
#pragma unroll
        for (int nt = 0; nt < 8; nt++)
#pragma unroll
            for (int i = 0; i < 4; i++) acc[mt][nt][i] = 0.f;
    float rs[4] = {0.f, 0.f, 0.f, 0.f};

    int cur = 0;
    for (int jt = 0; jt < NTILES; jt++) {
        const uint32_t stg = sbase + cur * STAGE_BYTES;
        const float2* edpm_s = (const float2*)(smraw + cur * STAGE_BYTES + ST_ED);
        const uint32_t* bits_s = (const uint32_t*)(smraw + cur * STAGE_BYTES + ST_BITS);

        if (jt == NTILES - 1) asm volatile("cp.async.wait_group 0;");
        else                  asm volatile("cp.async.wait_group 1;");
        __syncthreads();

        if (jt + 2 < NTILES) {
            int nxt = cur + 2; if (nxt >= 3) nxt -= 3;
            attn_prefetch(sbase + nxt * STAGE_BYTES, jt + 2, t, hsrc0, edbase, bitbase);
        }

        uint2 bw[4];
#pragma unroll
        for (int i = 0; i < 4; i++)
            bw[i] = *(const uint2*)&bits_s[(mg * 32 + gq + 8 * i) * 4 + khalf * 2];

#pragma unroll
        for (int ch = 0; ch < 4; ch++) {
            const int kk = khalf * 64 + ch * 16;
            const float4 lo = *(const float4*)&edpm_s[kk + 2 * tq];
            const float4 hi = *(const float4*)&edpm_s[kk + 2 * tq + 8];

            uint32_t afr[2][4];
#pragma unroll
            for (int mt = 0; mt < 2; mt++) {
#pragma unroll
                for (int rr = 0; rr < 2; rr++) {
                    const int i = mt * 2 + rr;
                    const uint32_t word = (ch < 2) ? bw[i].x : bw[i].y;
                    const uint32_t s = word >> (((ch & 1) << 4) + 2 * tq);
                    float w0 = fmaxf(Esp[i] * lo.x, Esm[i] * lo.y);
                    float w1 = fmaxf(Esp[i] * lo.z, Esm[i] * lo.w);
                    float w2 = fmaxf(Esp[i] * hi.x, Esm[i] * hi.y);
                    float w3 = fmaxf(Esp[i] * hi.z, Esm[i] * hi.w);
                    w0 = (s & 1u) ? w0 : 0.f;
                    w1 = (s & 2u) ? w1 : 0.f;
                    w2 = (s & 256u) ? w2 : 0.f;
                    w3 = (s & 512u) ? w3 : 0.f;
                    rs[i] += (w0 + w1) + (w2 + w3);
                    __half2 hp;
                    hp = __floats2half2_rn(w0, w1); afr[mt][rr] = *(uint32_t*)&hp;
                    hp = __floats2half2_rn(w2, w3); afr[mt][rr + 2] = *(uint32_t*)&hp;
                }
            }

#pragma unroll
            for (int p = 0; p < 4; p++) {
                uint32_t b0, b1, b2, b3;
                const uint32_t ad = stg + ldmOff + 2u * (p * 16 * TSH + ch * 16);
                asm volatile(
                    "ldmatrix.sync.aligned.m8n8.x4.shared.b16 {%0,%1,%2,%3}, [%4];"
                    : "=r"(b0), "=r"(b1), "=r"(b2), "=r"(b3) : "r"(ad));
#pragma unroll
                for (int mt = 0; mt < 2; mt++) {
                    asm volatile(
                        "mma.sync.aligned.m16n8k16.row.col.f32.f16.f16.f32 "
                        "{%0,%1,%2,%3},{%4,%5,%6,%7},{%8,%9},{%0,%1,%2,%3};"
                        : "+f"(acc[mt][2 * p][0]), "+f"(acc[mt][2 * p][1]),
                          "+f"(acc[mt][2 * p][2]), "+f"(acc[mt][2 * p][3])
                        : "r"(afr[mt][0]), "r"(afr[mt][1]), "r"(afr[mt][2]), "r"(afr[mt][3]),
                          "r"(b0), "r"(b1));
                    asm volatile(
                        "mma.sync.aligned.m16n8k16.row.col.f32.f16.f16.f32 "
                        "{%0,%1,%2,%3},{%4,%5,%6,%7},{%8,%9},{%0,%1,%2,%3};"
                        : "+f"(acc[mt][2 * p + 1][0]), "+f"(acc[mt][2 * p + 1][1]),
                          "+f"(acc[mt][2 * p + 1][2]), "+f"(acc[mt][2 * p + 1][3])
                        : "r"(afr[mt][0]), "r"(afr[mt][1]), "r"(afr[mt][2]), "r"(afr[mt][3]),
                          "r"(b2), "r"(b3));
                }
            }
        }
        cur = (cur == 2) ? 0 : cur + 1;
    }
    __syncthreads();

#pragma unroll
    for (int i = 0; i < 4; i++) {
        rs[i] += __shfl_xor_sync(0xffffffffu, rs[i], 1);
        rs[i] += __shfl_xor_sync(0xffffffffu, rs[i], 2);
    }

    float* red = (float*)smraw;
    const int ti = mg * 32 + lane;
    if (khalf == 1) {
        float* rp = red + ti * 68;
#pragma unroll
        for (int mt = 0; mt < 2; mt++)
#pragma unroll
            for (int nt = 0; nt < 8; nt++)
                *(float4*)&rp[mt * 32 + nt * 4] = *(float4*)&acc[mt][nt][0];
        *(float4*)&rp[64] = make_float4(rs[0], rs[1], rs[2], rs[3]);
    }
    __syncthreads();

    if (khalf == 0) {
        const float* rp = red + ti * 68;
#pragma unroll
        for (int mt = 0; mt < 2; mt++)
#pragma unroll
            for (int nt = 0; nt < 8; nt++) {
                float4 v = *(const float4*)&rp[mt * 32 + nt * 4];
                acc[mt][nt][0] += v.x; acc[mt][nt][1] += v.y;
                acc[mt][nt][2] += v.z; acc[mt][nt][3] += v.w;
            }
        float4 rv = *(const float4*)&rp[64];
        float inv[4];
        inv[0] = 1.f / (rs[0] + rv.x);
        inv[1] = 1.f / (rs[1] + rv.y);
        inv[2] = 1.f / (rs[2] + rv.z);
        inv[3] = 1.f / (rs[3] + rv.w);

#pragma unroll
        for (int mt = 0; mt < 2; mt++) {
            const int rA = m0 + mg * 32 + gq + 16 * mt;
            float* opA = out + (size_t)(b * Nx + rA) * (Hx * FOUT) + hh * FOUT;
            float* opB = opA + (size_t)8 * (Hx * FOUT);
            const float iA = inv[2 * mt], iB = inv[2 * mt + 1];
#pragma unroll
            for (int nt = 0; nt < 8; nt++) {
                float2 v0, v1;
                v0.x = acc[mt][nt][0] * iA; v0.y = acc[mt][nt][1] * iA;
                v1.x = acc[mt][nt][2] * iB; v1.y = acc[mt][nt][3] * iB;
                *(float2*)&opA[nt * 8 + 2 * tq] = v0;
                *(float2*)&opB[nt * 8 + 2 * tq] = v1;
            }
        }
    }
}

extern "C" void kernel_launch(void* const* d_in, const int* in_sizes, int n_in,
                              void* d_out, int out_size) {
    (void)in_sizes; (void)n_in; (void)out_size;
    const float* h   = (const float*)d_in[0];
    const float* adj = (const float*)d_in[1];
    const float* W   = (const float*)d_in[2];
    const float* a   = (const float*)d_in[3];
    float* out = (float*)d_out;

    cudaFuncSetAttribute(gat_proj_mma, cudaFuncAttributeMaxDynamicSharedMemorySize, SM_PROJ);
    cudaFuncSetAttribute(gat_attn_mma, cudaFuncAttributeMaxDynamicSharedMemorySize, SM_ATTN);

    prep_kernel<<<516, 256>>>(adj, W, a);
    gat_proj_mma<<<(Bx * Nx) / 64, 256, SM_PROJ>>>(h);
    dim3 grid(Nx / MT, Hx, Bx);
    gat_attn_mma<<<grid, 256, SM_ATTN>>>(out);
}